// round 2
// baseline (speedup 1.0000x reference)
#include <cuda_runtime.h>
#include <math.h>

// Problem constants
#define FH 256
#define FW 256
#define FC 256
#define FB 2
#define N_ROI 1024          // B*N = 2*512
#define OUT_H 7
#define OUT_W 7
#define NBINS 49            // 7*7
#define HALF_C 128          // channels per pooling block

// Scratch: NHWC-transposed feature map. 2*256*256*256 floats = 128 MB.
__device__ float g_xt[(size_t)FB * FH * FW * FC];

// Separately-rounded f32 ops (never FMA-contracted; match XLA HLO semantics)
__device__ __forceinline__ float mrn(float a, float b) { return __fmul_rn(a, b); }
__device__ __forceinline__ float arn(float a, float b) { return __fadd_rn(a, b); }

// ---------------------------------------------------------------------------
// Kernel 1: (B, C, H, W) -> (B, H*W, C) tiled transpose.
// ---------------------------------------------------------------------------
__global__ void transpose_kernel(const float* __restrict__ x) {
    __shared__ float tile[32][33];
    const int b  = blockIdx.z;
    const int p0 = blockIdx.x * 32;   // position tile (H*W dim)
    const int c0 = blockIdx.y * 32;   // channel tile
    const int tx = threadIdx.x;
    const int ty = threadIdx.y;

    const float* src = x    + (size_t)b * FC * FH * FW;
    float*       dst = g_xt + (size_t)b * FH * FW * FC;

#pragma unroll
    for (int j = 0; j < 32; j += 8)
        tile[ty + j][tx] = src[(size_t)(c0 + ty + j) * (FH * FW) + p0 + tx];
    __syncthreads();
#pragma unroll
    for (int j = 0; j < 32; j += 8)
        dst[(size_t)(p0 + ty + j) * FC + c0 + tx] = tile[tx][ty + j];
}

// ---------------------------------------------------------------------------
// Kernel 2: rotated ROI pool.
// Grid: (1024 rois, 2 channel-halves). Block: 128 threads.
// ---------------------------------------------------------------------------
__global__ void __launch_bounds__(128) rroi_pool_kernel(
    const float* __restrict__ boxes, float* __restrict__ out)
{
    __shared__ int   s_addr[NBINS][4];   // corner order: lt, rt, rb, lb ; -1 = invalid
    __shared__ float s_w[NBINS][4];
    __shared__ float s_out[HALF_C * NBINS];

    const int roi   = blockIdx.x;
    const int half  = blockIdx.y;
    const int tid   = threadIdx.x;
    const int cbase = half * HALF_C;

    if (tid < NBINS) {
        const float* bx = boxes + (size_t)roi * 5;
        const int b = roi >> 9;                 // N = 512 per batch

        const float cx  = mrn(bx[0], 0.25f);
        const float cy  = mrn(bx[1], 0.25f);
        const float w   = mrn(bx[2], 0.25f);
        const float h   = mrn(bx[3], 0.25f);
        const float ang = mrn(bx[4], (float)(M_PI / 180.0));

        // XLA lowers cos/sin to libdevice __nv_cosf/__nv_sinf == device cosf/sinf
        const float ca = cosf(ang);
        const float sa = sinf(ang);
        const float Sx = __fdiv_rn(w, (float)OUT_W);
        const float Sy = __fdiv_rn(h, (float)OUT_H);

        const float dx = -OUT_W / 2.0f;     // -3.5, exact
        const float dy = -OUT_H / 2.0f;     // -3.5, exact

        // Each op separately rounded, Python left-to-right association.
        const float M00 = mrn(ca, Sx);
        const float M01 = mrn(sa, Sy);
        const float M02 = arn(arn(mrn(M00, dx), mrn(M01, dy)), cx);
        const float M10 = mrn(-sa, Sx);
        const float M11 = mrn(ca, Sy);
        const float M12 = arn(arn(mrn(M10, dx), mrn(M11, dy)), cy);

        const int ph = tid / OUT_W;
        const int pw = tid % OUT_W;
        const float pwf = (float)pw;
        const float phf = (float)ph;

        float minX =  1e30f, maxX = -1e30f, minY = 1e30f, maxY = -1e30f;
#pragma unroll
        for (int k = 0; k < 4; ++k) {
            const float ox = (float)(k >> 1);   // offs[:,0] added to pw
            const float oy = (float)(k & 1);    // offs[:,1] added to ph
            const float px = pwf + ox;          // exact (small ints)
            const float py = phf + oy;          // exact
            // X = (M00*px + M01*py) + M02, each rounded separately
            const float X = arn(arn(mrn(M00, px), mrn(M01, py)), M02);
            const float Y = arn(arn(mrn(M10, px), mrn(M11, py)), M12);
            minX = fminf(minX, X); maxX = fmaxf(maxX, X);
            minY = fminf(minY, Y); maxY = fmaxf(maxY, Y);
        }

        // jnp.round == round-half-even == rintf
        const float leftMost   = fmaxf(rintf(minX), 0.0f);
        const float rightMost  = fminf(rintf(maxX), (float)(FW - 1));
        const float topMost    = fmaxf(rintf(minY), 0.0f);
        const float bottomMost = fminf(rintf(maxY), (float)(FH - 1));

        // Sums of small integers: exact. bcx/bcy are integer or half-integer.
        const float bcx = mrn(arn(leftMost, rightMost), 0.5f);
        const float bcy = mrn(arn(topMost, bottomMost), 0.5f);
        const int bl = (int)floorf(bcx);
        const int br = (int)ceilf(bcx);
        const int bt = (int)floorf(bcy);
        const int bb = (int)ceilf(bcy);
        const float rx = bcx - floorf(bcx);   // exactly 0.0 or 0.5
        const float ry = bcy - floorf(bcy);   // exactly 0.0 or 0.5

        // corner order matches reference accumulation: lt, rt, rb, lb
        const int ys[4] = { bt, bt, bb, bb };
        const int xs[4] = { bl, br, br, bl };
        const float ws[4] = { (1.0f - rx) * (1.0f - ry),
                              rx * (1.0f - ry),
                              rx * ry,
                              (1.0f - rx) * ry };          // all exact (pow2)
        const int pix_base = b * FH * FW;
#pragma unroll
        for (int k = 0; k < 4; ++k) {
            const int y = ys[k], x = xs[k];
            const bool valid = (y >= 0) && (y < FH) && (x >= 0) && (x < FW);
            s_addr[tid][k] = valid ? ((pix_base + y * FW + x) * FC) : -1;
            s_w[tid][k] = ws[k];
        }
    }
    __syncthreads();

    // Phase 2: gather + blend. Weights are powers of two -> muls exact, so
    // fmaf chain is bit-identical to the reference's separate mul/add chain.
#pragma unroll 1
    for (int bin = 0; bin < NBINS; ++bin) {
        const int a0 = s_addr[bin][0];
        const int a1 = s_addr[bin][1];
        const int a2 = s_addr[bin][2];
        const int a3 = s_addr[bin][3];
        const float w0 = s_w[bin][0];
        const float w1 = s_w[bin][1];
        const float w2 = s_w[bin][2];
        const float w3 = s_w[bin][3];

        float v = 0.0f;
        if (a0 >= 0) v = arn(v, mrn(__ldg(&g_xt[a0 + cbase + tid]), w0));
        if (a1 >= 0) v = arn(v, mrn(__ldg(&g_xt[a1 + cbase + tid]), w1));
        if (a2 >= 0) v = arn(v, mrn(__ldg(&g_xt[a2 + cbase + tid]), w2));
        if (a3 >= 0) v = arn(v, mrn(__ldg(&g_xt[a3 + cbase + tid]), w3));

        s_out[tid * NBINS + bin] = fmaxf(v, 0.0f);
    }
    __syncthreads();

    // Phase 3: coalesced flush of this (roi, channel-half) tile.
    float* dst = out + (size_t)roi * (FC * NBINS) + (size_t)cbase * NBINS;
#pragma unroll 4
    for (int i = tid; i < HALF_C * NBINS; i += HALF_C)
        dst[i] = s_out[i];
}

extern "C" void kernel_launch(void* const* d_in, const int* in_sizes, int n_in,
                              void* d_out, int out_size) {
    const float* x     = (const float*)d_in[0];   // (2,256,256,256) f32
    const float* boxes = (const float*)d_in[1];   // (2,512,5) f32
    float* out = (float*)d_out;                   // (1024,256,7,7) f32

    // 1) NCHW -> NHWC transpose into scratch
    transpose_kernel<<<dim3(FH * FW / 32, FC / 32, FB), dim3(32, 8)>>>(x);

    // 2) rotated ROI pool
    rroi_pool_kernel<<<dim3(N_ROI, 2), HALF_C>>>(boxes, out);
}

// round 3
// speedup vs baseline: 1.3074x; 1.3074x over previous
#include <cuda_runtime.h>
#include <math.h>

// Problem constants
#define FH 256
#define FW 256
#define FC 256
#define FB 2
#define N_ROI 1024          // B*N = 2*512
#define OUT_H 7
#define OUT_W 7
#define NBINS 49            // 7*7
#define HALF_C 128          // channels per pooling block

// Scratch: NHWC-transposed feature map. 2*256*256*256 floats = 128 MB.
__device__ float g_xt[(size_t)FB * FH * FW * FC];

// Separately-rounded f32 ops (never FMA-contracted; match XLA HLO semantics)
__device__ __forceinline__ float mrn(float a, float b) { return __fmul_rn(a, b); }
__device__ __forceinline__ float arn(float a, float b) { return __fadd_rn(a, b); }

// ---------------------------------------------------------------------------
// Kernel 1: (B, C, H, W) -> (B, H*W, C) tiled transpose.  (unchanged, proven)
// ---------------------------------------------------------------------------
__global__ void transpose_kernel(const float* __restrict__ x) {
    __shared__ float tile[32][33];
    const int b  = blockIdx.z;
    const int p0 = blockIdx.x * 32;   // position tile (H*W dim)
    const int c0 = blockIdx.y * 32;   // channel tile
    const int tx = threadIdx.x;
    const int ty = threadIdx.y;

    const float* src = x    + (size_t)b * FC * FH * FW;
    float*       dst = g_xt + (size_t)b * FH * FW * FC;

#pragma unroll
    for (int j = 0; j < 32; j += 8)
        tile[ty + j][tx] = src[(size_t)(c0 + ty + j) * (FH * FW) + p0 + tx];
    __syncthreads();
#pragma unroll
    for (int j = 0; j < 32; j += 8)
        dst[(size_t)(p0 + ty + j) * FC + c0 + tx] = tile[tx][ty + j];
}

// ---------------------------------------------------------------------------
// Kernel 2: rotated ROI pool.
// Grid: (1024 rois, 2 channel-halves). Block: 128 threads.
// Per thread: one channel. Bin loop: ph outer, pw fully unrolled -> 28
// unconditional independent LDGs in flight (invalid corners: weight = 0,
// address clamped in-range; x*0 contribution is exact).
// ---------------------------------------------------------------------------
__global__ void __launch_bounds__(128) rroi_pool_kernel(
    const float* __restrict__ boxes, float* __restrict__ out)
{
    __shared__ int   s_addr[NBINS][4];   // corner order: lt, rt, rb, lb (always valid addr)
    __shared__ float s_w[NBINS][4];      // weight, zeroed if corner invalid
    __shared__ float s_out[HALF_C * NBINS];

    const int roi   = blockIdx.x;
    const int half  = blockIdx.y;
    const int tid   = threadIdx.x;
    const int cbase = half * HALF_C;

    if (tid < NBINS) {
        const float* bx = boxes + (size_t)roi * 5;
        const int b = roi >> 9;                 // N = 512 per batch

        const float cx  = mrn(bx[0], 0.25f);
        const float cy  = mrn(bx[1], 0.25f);
        const float w   = mrn(bx[2], 0.25f);
        const float h   = mrn(bx[3], 0.25f);
        const float ang = mrn(bx[4], (float)(M_PI / 180.0));

        // XLA lowers cos/sin to libdevice __nv_cosf/__nv_sinf == device cosf/sinf
        const float ca = cosf(ang);
        const float sa = sinf(ang);
        const float Sx = __fdiv_rn(w, (float)OUT_W);
        const float Sy = __fdiv_rn(h, (float)OUT_H);

        const float dx = -OUT_W / 2.0f;     // -3.5, exact
        const float dy = -OUT_H / 2.0f;     // -3.5, exact

        // Each op separately rounded, Python left-to-right association.
        const float M00 = mrn(ca, Sx);
        const float M01 = mrn(sa, Sy);
        const float M02 = arn(arn(mrn(M00, dx), mrn(M01, dy)), cx);
        const float M10 = mrn(-sa, Sx);
        const float M11 = mrn(ca, Sy);
        const float M12 = arn(arn(mrn(M10, dx), mrn(M11, dy)), cy);

        const int ph = tid / OUT_W;
        const int pw = tid % OUT_W;
        const float pwf = (float)pw;
        const float phf = (float)ph;

        float minX =  1e30f, maxX = -1e30f, minY = 1e30f, maxY = -1e30f;
#pragma unroll
        for (int k = 0; k < 4; ++k) {
            const float ox = (float)(k >> 1);   // offs[:,0] added to pw
            const float oy = (float)(k & 1);    // offs[:,1] added to ph
            const float px = pwf + ox;          // exact (small ints)
            const float py = phf + oy;          // exact
            const float X = arn(arn(mrn(M00, px), mrn(M01, py)), M02);
            const float Y = arn(arn(mrn(M10, px), mrn(M11, py)), M12);
            minX = fminf(minX, X); maxX = fmaxf(maxX, X);
            minY = fminf(minY, Y); maxY = fmaxf(maxY, Y);
        }

        // jnp.round == round-half-even == rintf
        const float leftMost   = fmaxf(rintf(minX), 0.0f);
        const float rightMost  = fminf(rintf(maxX), (float)(FW - 1));
        const float topMost    = fmaxf(rintf(minY), 0.0f);
        const float bottomMost = fminf(rintf(maxY), (float)(FH - 1));

        const float bcx = mrn(arn(leftMost, rightMost), 0.5f);
        const float bcy = mrn(arn(topMost, bottomMost), 0.5f);
        const int bl = (int)floorf(bcx);
        const int br = (int)ceilf(bcx);
        const int bt = (int)floorf(bcy);
        const int bb = (int)ceilf(bcy);
        const float rx = bcx - floorf(bcx);   // exactly 0.0 or 0.5
        const float ry = bcy - floorf(bcy);   // exactly 0.0 or 0.5

        // corner order matches reference accumulation: lt, rt, rb, lb
        const int ys[4] = { bt, bt, bb, bb };
        const int xs[4] = { bl, br, br, bl };
        const float ws[4] = { (1.0f - rx) * (1.0f - ry),
                              rx * (1.0f - ry),
                              rx * ry,
                              (1.0f - rx) * ry };          // all exact (pow2)
        const int pix_base = b * FH * FW;
#pragma unroll
        for (int k = 0; k < 4; ++k) {
            const int y = ys[k], x = xs[k];
            const bool valid = (y >= 0) && (y < FH) && (x >= 0) && (x < FW);
            const int yc = min(max(y, 0), FH - 1);
            const int xc = min(max(x, 0), FW - 1);
            s_addr[tid][k] = (pix_base + yc * FW + xc) * FC;   // always in-range
            s_w[tid][k]    = valid ? ws[k] : 0.0f;             // mask via weight
        }
    }
    __syncthreads();

    // Phase 2: gather + blend. ph outer (no unroll), pw fully unrolled
    // -> 28 independent unconditional loads in flight per thread.
    const int cidx = cbase + tid;
#pragma unroll 1
    for (int ph = 0; ph < OUT_H; ++ph) {
        float v[OUT_W];
#pragma unroll
        for (int pw = 0; pw < OUT_W; ++pw) {
            const int bin = ph * OUT_W + pw;
            const float x0 = __ldg(&g_xt[s_addr[bin][0] + cidx]);
            const float x1 = __ldg(&g_xt[s_addr[bin][1] + cidx]);
            const float x2 = __ldg(&g_xt[s_addr[bin][2] + cidx]);
            const float x3 = __ldg(&g_xt[s_addr[bin][3] + cidx]);
            float t = 0.0f;
            t = arn(t, mrn(x0, s_w[bin][0]));
            t = arn(t, mrn(x1, s_w[bin][1]));
            t = arn(t, mrn(x2, s_w[bin][2]));
            t = arn(t, mrn(x3, s_w[bin][3]));
            v[pw] = fmaxf(t, 0.0f);
        }
#pragma unroll
        for (int pw = 0; pw < OUT_W; ++pw)
            s_out[tid * NBINS + ph * OUT_W + pw] = v[pw];   // stride 49: conflict-free
    }
    __syncthreads();

    // Phase 3: coalesced flush of this (roi, channel-half) tile.
    float* dst = out + (size_t)roi * (FC * NBINS) + (size_t)cbase * NBINS;
#pragma unroll 4
    for (int i = tid; i < HALF_C * NBINS; i += HALF_C)
        dst[i] = s_out[i];
}

extern "C" void kernel_launch(void* const* d_in, const int* in_sizes, int n_in,
                              void* d_out, int out_size) {
    const float* x     = (const float*)d_in[0];   // (2,256,256,256) f32
    const float* boxes = (const float*)d_in[1];   // (2,512,5) f32
    float* out = (float*)d_out;                   // (1024,256,7,7) f32

    // 1) NCHW -> NHWC transpose into scratch
    transpose_kernel<<<dim3(FH * FW / 32, FC / 32, FB), dim3(32, 8)>>>(x);

    // 2) rotated ROI pool
    rroi_pool_kernel<<<dim3(N_ROI, 2), HALF_C>>>(boxes, out);
}

// round 5
// speedup vs baseline: 1.4570x; 1.1145x over previous
#include <cuda_runtime.h>
#include <math.h>

// Problem constants
#define FH 256
#define FW 256
#define FC 256
#define FB 2
#define N_ROI 1024          // B*N = 2*512
#define OUT_H 7
#define OUT_W 7
#define NBINS 49            // 7*7
#define HALF_C 128          // channels per pooling block

// Scratch: NHWC-transposed feature map. 2*256*256*256 floats = 128 MB.
__device__ float g_xt[(size_t)FB * FH * FW * FC];

// Separately-rounded f32 ops (never FMA-contracted; match XLA HLO semantics)
__device__ __forceinline__ float mrn(float a, float b) { return __fmul_rn(a, b); }
__device__ __forceinline__ float arn(float a, float b) { return __fadd_rn(a, b); }

// ---------------------------------------------------------------------------
// Kernel 1: (B, C, H, W) -> (B, H*W, C) transpose, float4 + XOR swizzle.
// Tile: 32 channels x 128 pixels. Block (32,8). Grid (P/128, C/32, B).
// smem: float4 tile4[c][col], physical col = p4 ^ c (p4 = pixel-group 0..31).
//   - STS.128: per 16B phase, word offsets 4*(tx^c) -> all banks once. CF.
//   - LDS.128: lanes read tile4[tx][p4^tx] -> same bijection. CF.
//   - STG.32 x4: each instruction writes 32 consecutive floats (128B).
// ---------------------------------------------------------------------------
__global__ void __launch_bounds__(256) transpose_kernel(const float* __restrict__ x) {
    __shared__ float4 tile4[32][32];
    const int b  = blockIdx.z;
    const int p0 = blockIdx.x * 128;  // pixel tile (H*W dim)
    const int c0 = blockIdx.y * 32;   // channel tile
    const int tx = threadIdx.x;       // 0..31
    const int ty = threadIdx.y;       // 0..7

    const float* src = x    + (size_t)b * FC * FH * FW;
    float*       dst = g_xt + (size_t)b * FH * FW * FC;

    // Load: thread -> channel c_local, pixels p0+4tx..+3
#pragma unroll
    for (int j = 0; j < 4; ++j) {
        const int c_local = ty + 8 * j;
        const float4 v = *reinterpret_cast<const float4*>(
            src + (size_t)(c0 + c_local) * (FH * FW) + p0 + 4 * tx);
        tile4[c_local][tx ^ c_local] = v;
    }
    __syncthreads();

    // Store: thread -> channel c0+tx, pixel-group p4 (4 pixels)
#pragma unroll
    for (int j = 0; j < 4; ++j) {
        const int p4 = ty + 8 * j;                 // 0..31
        const float4 v = tile4[tx][p4 ^ tx];
        float* d = dst + (size_t)(p0 + 4 * p4) * FC + c0 + tx;
        d[0 * FC] = v.x;
        d[1 * FC] = v.y;
        d[2 * FC] = v.z;
        d[3 * FC] = v.w;
    }
}

// ---------------------------------------------------------------------------
// Kernel 2: rotated ROI pool. (unchanged from R3 — proven, bit-exact)
// ---------------------------------------------------------------------------
__global__ void __launch_bounds__(128) rroi_pool_kernel(
    const float* __restrict__ boxes, float* __restrict__ out)
{
    __shared__ int   s_addr[NBINS][4];   // corner order: lt, rt, rb, lb (always valid addr)
    __shared__ float s_w[NBINS][4];      // weight, zeroed if corner invalid
    __shared__ float s_out[HALF_C * NBINS];

    const int roi   = blockIdx.x;
    const int half  = blockIdx.y;
    const int tid   = threadIdx.x;
    const int cbase = half * HALF_C;

    if (tid < NBINS) {
        const float* bx = boxes + (size_t)roi * 5;
        const int b = roi >> 9;                 // N = 512 per batch

        const float cx  = mrn(bx[0], 0.25f);
        const float cy  = mrn(bx[1], 0.25f);
        const float w   = mrn(bx[2], 0.25f);
        const float h   = mrn(bx[3], 0.25f);
        const float ang = mrn(bx[4], (float)(M_PI / 180.0));

        const float ca = cosf(ang);
        const float sa = sinf(ang);
        const float Sx = __fdiv_rn(w, (float)OUT_W);
        const float Sy = __fdiv_rn(h, (float)OUT_H);

        const float dx = -OUT_W / 2.0f;     // -3.5, exact
        const float dy = -OUT_H / 2.0f;     // -3.5, exact

        const float M00 = mrn(ca, Sx);
        const float M01 = mrn(sa, Sy);
        const float M02 = arn(arn(mrn(M00, dx), mrn(M01, dy)), cx);
        const float M10 = mrn(-sa, Sx);
        const float M11 = mrn(ca, Sy);
        const float M12 = arn(arn(mrn(M10, dx), mrn(M11, dy)), cy);

        const int ph = tid / OUT_W;
        const int pw = tid % OUT_W;
        const float pwf = (float)pw;
        const float phf = (float)ph;

        float minX =  1e30f, maxX = -1e30f, minY = 1e30f, maxY = -1e30f;
#pragma unroll
        for (int k = 0; k < 4; ++k) {
            const float ox = (float)(k >> 1);   // offs[:,0] added to pw
            const float oy = (float)(k & 1);    // offs[:,1] added to ph
            const float px = pwf + ox;          // exact (small ints)
            const float py = phf + oy;          // exact
            const float X = arn(arn(mrn(M00, px), mrn(M01, py)), M02);
            const float Y = arn(arn(mrn(M10, px), mrn(M11, py)), M12);
            minX = fminf(minX, X); maxX = fmaxf(maxX, X);
            minY = fminf(minY, Y); maxY = fmaxf(maxY, Y);
        }

        // jnp.round == round-half-even == rintf
        const float leftMost   = fmaxf(rintf(minX), 0.0f);
        const float rightMost  = fminf(rintf(maxX), (float)(FW - 1));
        const float topMost    = fmaxf(rintf(minY), 0.0f);
        const float bottomMost = fminf(rintf(maxY), (float)(FH - 1));

        const float bcx = mrn(arn(leftMost, rightMost), 0.5f);
        const float bcy = mrn(arn(topMost, bottomMost), 0.5f);
        const int bl = (int)floorf(bcx);
        const int br = (int)ceilf(bcx);
        const int bt = (int)floorf(bcy);
        const int bb = (int)ceilf(bcy);
        const float rx = bcx - floorf(bcx);   // exactly 0.0 or 0.5
        const float ry = bcy - floorf(bcy);   // exactly 0.0 or 0.5

        // corner order matches reference accumulation: lt, rt, rb, lb
        const int ys[4] = { bt, bt, bb, bb };
        const int xs[4] = { bl, br, br, bl };
        const float ws[4] = { (1.0f - rx) * (1.0f - ry),
                              rx * (1.0f - ry),
                              rx * ry,
                              (1.0f - rx) * ry };          // all exact (pow2)
        const int pix_base = b * FH * FW;
#pragma unroll
        for (int k = 0; k < 4; ++k) {
            const int y = ys[k], x = xs[k];
            const bool valid = (y >= 0) && (y < FH) && (x >= 0) && (x < FW);
            const int yc = min(max(y, 0), FH - 1);
            const int xc = min(max(x, 0), FW - 1);
            s_addr[tid][k] = (pix_base + yc * FW + xc) * FC;   // always in-range
            s_w[tid][k]    = valid ? ws[k] : 0.0f;             // mask via weight
        }
    }
    __syncthreads();

    // Phase 2: gather + blend. ph outer (no unroll), pw fully unrolled
    // -> 28 independent unconditional loads in flight per thread.
    const int cidx = cbase + tid;
#pragma unroll 1
    for (int ph = 0; ph < OUT_H; ++ph) {
        float v[OUT_W];
#pragma unroll
        for (int pw = 0; pw < OUT_W; ++pw) {
            const int bin = ph * OUT_W + pw;
            const float x0 = __ldg(&g_xt[s_addr[bin][0] + cidx]);
            const float x1 = __ldg(&g_xt[s_addr[bin][1] + cidx]);
            const float x2 = __ldg(&g_xt[s_addr[bin][2] + cidx]);
            const float x3 = __ldg(&g_xt[s_addr[bin][3] + cidx]);
            float t = 0.0f;
            t = arn(t, mrn(x0, s_w[bin][0]));
            t = arn(t, mrn(x1, s_w[bin][1]));
            t = arn(t, mrn(x2, s_w[bin][2]));
            t = arn(t, mrn(x3, s_w[bin][3]));
            v[pw] = fmaxf(t, 0.0f);
        }
#pragma unroll
        for (int pw = 0; pw < OUT_W; ++pw)
            s_out[tid * NBINS + ph * OUT_W + pw] = v[pw];   // stride 49: conflict-free
    }
    __syncthreads();

    // Phase 3: coalesced flush of this (roi, channel-half) tile.
    float* dst = out + (size_t)roi * (FC * NBINS) + (size_t)cbase * NBINS;
#pragma unroll 4
    for (int i = tid; i < HALF_C * NBINS; i += HALF_C)
        dst[i] = s_out[i];
}

extern "C" void kernel_launch(void* const* d_in, const int* in_sizes, int n_in,
                              void* d_out, int out_size) {
    const float* x     = (const float*)d_in[0];   // (2,256,256,256) f32
    const float* boxes = (const float*)d_in[1];   // (2,512,5) f32
    float* out = (float*)d_out;                   // (1024,256,7,7) f32

    // 1) NCHW -> NHWC transpose into scratch (float4 both sides via swizzle)
    transpose_kernel<<<dim3(FH * FW / 128, FC / 32, FB), dim3(32, 8)>>>(x);

    // 2) rotated ROI pool
    rroi_pool_kernel<<<dim3(N_ROI, 2), HALF_C>>>(boxes, out);
}